// round 8
// baseline (speedup 1.0000x reference)
#include <cuda_runtime.h>
#include <cuda_bf16.h>
#include <cstdint>

#define THREADS 256
#define NCHUNK  128    // K = 8192, chunk = 64 fp32

__device__ __align__(256) float g_x32[128 * 8192];   // tf32-rounded x

__device__ __forceinline__ uint32_t smem_u32(const void* p) {
    uint32_t a;
    asm("{ .reg .u64 t; cvta.to.shared.u64 t, %1; cvt.u32.u64 %0, t; }" : "=r"(a) : "l"(p));
    return a;
}
__device__ __forceinline__ int sign_neg(int a, int b) {  // 1 if e_a*e_b negative
    int t = a >> 1, c = 0;
    while (t) { c += __popc(t & b); t >>= 1; }
    return c & 1;
}
__device__ __forceinline__ void ldsm4(uint32_t& r0, uint32_t& r1, uint32_t& r2, uint32_t& r3,
                                      uint32_t addr) {
    asm volatile("ldmatrix.sync.aligned.m8n8.x4.shared.b16 {%0,%1,%2,%3}, [%4];"
                 : "=r"(r0), "=r"(r1), "=r"(r2), "=r"(r3) : "r"(addr));
}
// a[] in ldsm matrix order {m0,m1,m2,m3}; mma wants {m0,m2,m1,m3}
__device__ __forceinline__ void mma_tf32(float* d, const uint32_t* a, const uint32_t* b) {
    asm volatile(
        "mma.sync.aligned.m16n8k8.row.col.f32.tf32.tf32.f32 "
        "{%0,%1,%2,%3}, {%4,%5,%6,%7}, {%8,%9}, {%0,%1,%2,%3};"
        : "+f"(d[0]), "+f"(d[1]), "+f"(d[2]), "+f"(d[3])
        : "r"(a[0]), "r"(a[2]), "r"(a[1]), "r"(a[3]), "r"(b[0]), "r"(b[1]));
}
__device__ __forceinline__ void cpasync16(uint32_t dst, const void* src) {
    asm volatile("cp.async.cg.shared.global [%0], [%1], 16;" :: "r"(dst), "l"(src) : "memory");
}
__device__ __forceinline__ uint32_t tf32u(float v) {
    uint32_t o;
    asm("cvt.rna.tf32.f32 %0, %1;" : "=r"(o) : "f"(v));
    return o;
}

// ---------- fp32 -> tf32-rounded fp32 (x only; w rounded in-kernel) ----------
__global__ void round_x(const float* __restrict__ src) {
    int i = blockIdx.x * blockDim.x + threadIdx.x;  // < 262144
    float4 v = reinterpret_cast<const float4*>(src)[i];
    uint4 o{tf32u(v.x), tf32u(v.y), tf32u(v.z), tf32u(v.w)};
    reinterpret_cast<uint4*>(g_x32)[i] = o;
}

// ---------- main GEMM: D[128 x 64] per CTA, K = 8192, tf32, chunk=64 ----------
__global__ void __launch_bounds__(THREADS, 1)
ga_gemm(const float* __restrict__ w, const float* __restrict__ bias,
        float* __restrict__ out) {
    // dynamic smem: A0[32K] A1[32K] B0[16K] B1[16K] = 96KB (rows of 64 fp32 = 256B)
    extern __shared__ __align__(1024) uint8_t smem[];
    const int tid = threadIdx.x, wid = tid >> 5, lid = tid & 31, bx = blockIdx.x;
    const int wm = wid >> 1, wn = wid & 1;  // 4(M) x 2(N) warp grid, warp tile 32x32

    const uint32_t base = smem_u32(smem);
    const uint32_t sA[2] = {base, base + 32768};
    const uint32_t sB[2] = {base + 65536, base + 81920};

    // ---- B-build constants: thread -> row j=(uu,kk), 16 dest cols (one n) ----
    const int j = tid >> 2, sub = tid & 3;
    const int kk = j & 15, uu = j >> 4;
    const int u = bx * 4 + uu;
    const int kkhi = kk >> 2, kb01 = kk & 3;
    uint32_t msk[16];
#pragma unroll
    for (int i = 0; i < 16; i++)
        msk[i] = sign_neg(i, i ^ kk) ? 0x80000000u : 0u;
    uint32_t sts[4];
#pragma unroll
    for (int dq = 0; dq < 4; dq++)
        sts[dq] = (uint32_t)(j * 256 + ((4 * sub + dq) ^ (j & 7)) * 16);
    const float* wthread = w + u * 8192 + sub * 16;

    // ---- A cp.async addressing: 2048 x 16B blocks, 8 per thread ----
    int agoff[8];
    uint32_t aswz[8];
#pragma unroll
    for (int q = 0; q < 8; q++) {
        int idx = q * 256 + tid;
        int r = idx >> 4, b = idx & 15;
        agoff[q] = r * 8192 + b * 4;  // fp32 elements
        aswz[q] = (uint32_t)(r * 256 + ((b ^ (r & 7)) * 16));
    }

    // ---- ldmatrix address tables (buffer-relative) ----
    uint32_t aoff[2][8], boff[2][8];
#pragma unroll
    for (int mt = 0; mt < 2; mt++)
#pragma unroll
        for (int ks = 0; ks < 8; ks++) {
            int r = wm * 32 + mt * 16 + ((lid >> 4) & 1) * 8 + (lid & 7);
            int blk = 2 * ks + ((lid >> 3) & 1);
            aoff[mt][ks] = (uint32_t)(r * 256 + ((blk ^ (lid & 7)) * 16));
        }
#pragma unroll
    for (int g = 0; g < 2; g++)
#pragma unroll
        for (int ks = 0; ks < 8; ks++) {
            int n = wn * 32 + g * 16 + ((lid >> 4) & 1) * 8 + (lid & 7);
            int blk = 2 * ks + ((lid >> 3) & 1);
            boff[g][ks] = (uint32_t)(n * 256 + ((blk ^ (lid & 7)) * 16));
        }

    float d[2][4][4];
#pragma unroll
    for (int a = 0; a < 2; a++)
#pragma unroll
        for (int b = 0; b < 4; b++)
#pragma unroll
            for (int c = 0; c < 4; c++) d[a][b][c] = 0.f;

    // load w quads (pre-permuted: quad q <- source quad q^kkhi), tf32-round,
    // apply low-2-blade-bit component swaps
    uint4 V[4];
    auto load_prep = [&](int koff) {
#pragma unroll
        for (int q = 0; q < 4; q++) {
            float4 s = *reinterpret_cast<const float4*>(wthread + koff + ((q ^ kkhi) << 2));
            V[q] = make_uint4(tf32u(s.x), tf32u(s.y), tf32u(s.z), tf32u(s.w));
        }
        if (kb01 & 1) {  // swap adjacent components
#pragma unroll
            for (int q = 0; q < 4; q++) {
                uint32_t t;
                t = V[q].x; V[q].x = V[q].y; V[q].y = t;
                t = V[q].z; V[q].z = V[q].w; V[q].w = t;
            }
        }
        if (kb01 & 2) {  // swap component pairs
#pragma unroll
            for (int q = 0; q < 4; q++) {
                uint32_t t;
                t = V[q].x; V[q].x = V[q].z; V[q].z = t;
                t = V[q].y; V[q].y = V[q].w; V[q].w = t;
            }
        }
    };

    // ---- prologue: stage chunk 0 ----
#pragma unroll
    for (int q = 0; q < 8; q++) cpasync16(sA[0] + aswz[q], g_x32 + agoff[q]);
    asm volatile("cp.async.commit_group;" ::: "memory");
    load_prep(0);

    for (int c = 0; c < NCHUNK; c++) {
        const int cur = c & 1;
        asm volatile("cp.async.wait_group 0;" ::: "memory");
        // ---- B tile: sign-XOR the pre-permuted w quads, store ----
        {
            uint8_t* bbuf = smem + 65536 + (cur << 14);
#pragma unroll
            for (int dq = 0; dq < 4; dq++) {
                uint4 o = V[dq];
                o.x ^= msk[4 * dq + 0];
                o.y ^= msk[4 * dq + 1];
                o.z ^= msk[4 * dq + 2];
                o.w ^= msk[4 * dq + 3];
                *reinterpret_cast<uint4*>(bbuf + sts[dq]) = o;
            }
        }
        __syncthreads();
        // ---- prefetch chunk c+1 ----
        if (c + 1 < NCHUNK) {
            const int koffn = (c + 1) * 64;
#pragma unroll
            for (int q = 0; q < 8; q++)
                cpasync16(sA[cur ^ 1] + aswz[q], g_x32 + agoff[q] + koffn);
            asm volatile("cp.async.commit_group;" ::: "memory");
            load_prep(koffn);
        }
        // ---- compute: 8 k-steps (k8) x (2 m-tiles x 4 n-tiles) ----
#pragma unroll
        for (int ks = 0; ks < 8; ks++) {
            uint32_t A0[4], A1[4], Bq0[4], Bq1[4];
            ldsm4(A0[0], A0[1], A0[2], A0[3], sA[cur] + aoff[0][ks]);
            ldsm4(A1[0], A1[1], A1[2], A1[3], sA[cur] + aoff[1][ks]);
            ldsm4(Bq0[0], Bq0[1], Bq0[2], Bq0[3], sB[cur] + boff[0][ks]);
            ldsm4(Bq1[0], Bq1[1], Bq1[2], Bq1[3], sB[cur] + boff[1][ks]);
            mma_tf32(d[0][0], A0, Bq0 + 0);
            mma_tf32(d[0][1], A0, Bq0 + 2);
            mma_tf32(d[0][2], A0, Bq1 + 0);
            mma_tf32(d[0][3], A0, Bq1 + 2);
            mma_tf32(d[1][0], A1, Bq0 + 0);
            mma_tf32(d[1][1], A1, Bq0 + 2);
            mma_tf32(d[1][2], A1, Bq1 + 0);
            mma_tf32(d[1][3], A1, Bq1 + 2);
        }
    }

    // ---- epilogue: D + bias -> out ----
#pragma unroll
    for (int mt = 0; mt < 2; mt++) {
        const int m0 = wm * 32 + mt * 16 + (lid >> 2);
#pragma unroll
        for (int nt = 0; nt < 4; nt++) {
            const int nc = bx * 64 + wn * 32 + nt * 8 + 2 * (lid & 3);
            const float2 bb = *reinterpret_cast<const float2*>(bias + nc);
            float2 v0{d[mt][nt][0] + bb.x, d[mt][nt][1] + bb.y};
            float2 v1{d[mt][nt][2] + bb.x, d[mt][nt][3] + bb.y};
            *reinterpret_cast<float2*>(out + (size_t)m0 * 8192 + nc) = v0;
            *reinterpret_cast<float2*>(out + (size_t)(m0 + 8) * 8192 + nc) = v1;
        }
    }
}

extern "C" void kernel_launch(void* const* d_in, const int* in_sizes, int n_in,
                              void* d_out, int out_size) {
    // Dispatch inputs by element count (robust to metadata ordering):
    //   x: 1048576, w: 4194304, b: 8192, cayley: 4096
    const float* x = nullptr;
    const float* w = nullptr;
    const float* bias = nullptr;
    for (int i = 0; i < n_in; i++) {
        if (in_sizes[i] == 1048576)      x    = (const float*)d_in[i];
        else if (in_sizes[i] == 4194304) w    = (const float*)d_in[i];
        else if (in_sizes[i] == 8192)    bias = (const float*)d_in[i];
    }
    float* out = (float*)d_out;

    static bool configured = false;
    if (!configured) {
        cudaFuncSetAttribute(ga_gemm, cudaFuncAttributeMaxDynamicSharedMemorySize, 98304);
        configured = true;
    }

    round_x<<<1024, 256>>>(x);
    ga_gemm<<<128, THREADS, 98304>>>(w, bias, out);
}